// round 5
// baseline (speedup 1.0000x reference)
#include <cuda_runtime.h>
#include <math.h>

#define NN 50000
#define EE 800000
#define HH 128
#define SS 5000
#define GG 64
#define PAD 132   // smem row stride for gathered A tile (bank-staggered)

// Scratch (device globals: no allocation allowed)
__device__ float g_h   [NN*HH];
__device__ float g_h2  [NN*HH];
__device__ float g_pool[(SS+GG)*HH];
__device__ int   g_rowptr[NN+1];
__device__ int   g_cur[NN];
__device__ int   g_csr[EE];
__device__ int   g_bsum[64];

// ---------------------------------------------------------------------------
// packed f32x2 helpers
__device__ __forceinline__ unsigned long long pack2(float lo, float hi) {
    unsigned long long r;
    asm("mov.b64 %0, {%1, %2};" : "=l"(r) : "f"(lo), "f"(hi));
    return r;
}
__device__ __forceinline__ unsigned long long fma2(unsigned long long a,
                                                   unsigned long long b,
                                                   unsigned long long c) {
    unsigned long long d;
    asm("fma.rn.f32x2 %0, %1, %2, %3;" : "=l"(d) : "l"(a), "l"(b), "l"(c));
    return d;
}
__device__ __forceinline__ float2 unpack2(unsigned long long v) {
    float2 f;
    asm("mov.b64 {%0, %1}, %2;" : "=f"(f.x), "=f"(f.y) : "l"(v));
    return f;
}

// ---------------------------------------------------------------------------
__global__ void init_zero(int* __restrict__ rowptr, float4* __restrict__ pool) {
    int i = blockIdx.x * blockDim.x + threadIdx.x;
    if (i < NN + 1) rowptr[i] = 0;
    if (i < (SS + GG) * HH / 4) pool[i] = make_float4(0.f, 0.f, 0.f, 0.f);
}

__global__ void hist_dst(const int* __restrict__ dst) {
    int e = blockIdx.x * blockDim.x + threadIdx.x;
    if (e < EE) atomicAdd(&g_rowptr[dst[e] + 1], 1);
}

__global__ void scan1(int* __restrict__ data, int* __restrict__ bsum, int n) {
    __shared__ int sh[1024];
    int gid = blockIdx.x * 1024 + threadIdx.x;
    int v = (gid < n) ? data[gid] : 0;
    sh[threadIdx.x] = v;
    __syncthreads();
    for (int off = 1; off < 1024; off <<= 1) {
        int t = (threadIdx.x >= off) ? sh[threadIdx.x - off] : 0;
        __syncthreads();
        sh[threadIdx.x] += t;
        __syncthreads();
    }
    if (gid < n) data[gid] = sh[threadIdx.x];
    if (threadIdx.x == 1023) bsum[blockIdx.x] = sh[1023];
}

__global__ void scan_finish(int* __restrict__ data, const int* __restrict__ bsum,
                            int* __restrict__ cur, int n) {
    __shared__ int offs;
    if (threadIdx.x == 0) {
        int s = 0;
        for (int j = 0; j < blockIdx.x; j++) s += bsum[j];
        offs = s;
    }
    __syncthreads();
    int gid = blockIdx.x * 1024 + threadIdx.x;
    if (gid < n) {
        int v = data[gid] + offs;
        data[gid] = v;
        if (gid < NN) cur[gid] = v;
    }
}

__global__ void fill_csr(const int* __restrict__ src, const int* __restrict__ dst) {
    int e = blockIdx.x * blockDim.x + threadIdx.x;
    if (e >= EE) return;
    int d = dst[e];
    int pos = atomicAdd(&g_cur[d], 1);
    g_csr[pos] = src[e];
}

// ---------------------------------------------------------------------------
// Fully fused GIN conv:
//   phase 0: CSR gather  agg[r] = A[r] + sum_{s in N(r)} A[s]   (into smem)
//   phase 1: H1 = relu(agg @ Wa + ba)                           (H1 tile in smem)
//   phase 2: C  = relu(H1 @ Wb + bb)
// CONV1: A has 2 features; gather + first linear specialized.
// POOL:  instead of writing C, atomicAdd rows into poolOut[seg[row]].
template<bool CONV1, bool POOL>
__global__ void __launch_bounds__(256, 2)
gin_conv(const float* __restrict__ A, const float* __restrict__ Wa,
         const float* __restrict__ ba, const float* __restrict__ Wb,
         const float* __restrict__ bb, float* __restrict__ C,
         const int* __restrict__ seg, float* __restrict__ poolOut) {
    extern __shared__ float sm[];
    float* AggT = sm;                                  // [128][PAD] row-major
    float* H1t  = sm;                                  // reused after phase 1
    float (*As)[128] = (float(*)[128])(sm + 128 * PAD);
    float (*Ws)[128] = (float(*)[128])(sm + 128 * PAD + 2048);

    const int tid = threadIdx.x;
    const int tm = (tid >> 4) * 8;
    const int tn = (tid & 15) * 8;
    const int rowBase = blockIdx.x * 128;

    const int lr = tid >> 1;
    const int lk = (tid & 1) * 8;
    const int wr = tid >> 5;
    const int wc = (tid & 31) * 4;

    float o1[8][8];

    if (CONV1) {
        if (tid < 128) {
            int grow = rowBase + tid;
            float2 acc = make_float2(0.f, 0.f);
            if (grow < NN) {
                acc = *(const float2*)(A + 2 * (size_t)grow);
                int p = g_rowptr[grow], e = g_rowptr[grow + 1];
                for (; p + 3 < e; p += 4) {
                    float2 v0 = *(const float2*)(A + 2 * (size_t)g_csr[p]);
                    float2 v1 = *(const float2*)(A + 2 * (size_t)g_csr[p + 1]);
                    float2 v2 = *(const float2*)(A + 2 * (size_t)g_csr[p + 2]);
                    float2 v3 = *(const float2*)(A + 2 * (size_t)g_csr[p + 3]);
                    acc.x += (v0.x + v1.x) + (v2.x + v3.x);
                    acc.y += (v0.y + v1.y) + (v2.y + v3.y);
                }
                for (; p < e; ++p) {
                    float2 v = *(const float2*)(A + 2 * (size_t)g_csr[p]);
                    acc.x += v.x; acc.y += v.y;
                }
            }
            AggT[tid * 2]     = acc.x;
            AggT[tid * 2 + 1] = acc.y;
        }
        __syncthreads();

        float4 wa0 = *(const float4*)(Wa + tn);
        float4 wa1 = *(const float4*)(Wa + tn + 4);
        float4 wb0 = *(const float4*)(Wa + HH + tn);
        float4 wb1 = *(const float4*)(Wa + HH + tn + 4);
        float4 b0  = *(const float4*)(ba + tn);
        float4 b1  = *(const float4*)(ba + tn + 4);
        float w0v[8] = {wa0.x, wa0.y, wa0.z, wa0.w, wa1.x, wa1.y, wa1.z, wa1.w};
        float w1v[8] = {wb0.x, wb0.y, wb0.z, wb0.w, wb1.x, wb1.y, wb1.z, wb1.w};
        float bv[8]  = {b0.x, b0.y, b0.z, b0.w, b1.x, b1.y, b1.z, b1.w};
        float a0v[8], a1v[8];
#pragma unroll
        for (int i = 0; i < 8; i++) {
            a0v[i] = AggT[(tm + i) * 2];
            a1v[i] = AggT[(tm + i) * 2 + 1];
        }
        __syncthreads();  // done reading AggT before H1t overwrite
#pragma unroll
        for (int i = 0; i < 8; i++)
#pragma unroll
            for (int c = 0; c < 8; c++)
                o1[i][c] = fmaxf(fmaf(a0v[i], w0v[c], fmaf(a1v[i], w1v[c], bv[c])), 0.f);
    } else {
        {
            const int wid = tid >> 5;
            const int lane = tid & 31;
            const float* hp = A + lane * 4;
#pragma unroll 1
            for (int j = 0; j < 16; j++) {
                int r = wid + j * 8;
                int grow = rowBase + r;
                float4 acc = make_float4(0.f, 0.f, 0.f, 0.f);
                if (grow < NN) {
                    acc = *(const float4*)(hp + (size_t)grow * HH);
                    int p = g_rowptr[grow], e = g_rowptr[grow + 1];
                    for (; p + 3 < e; p += 4) {
                        int s0 = g_csr[p], s1 = g_csr[p + 1];
                        int s2 = g_csr[p + 2], s3 = g_csr[p + 3];
                        float4 v0 = *(const float4*)(hp + (size_t)s0 * HH);
                        float4 v1 = *(const float4*)(hp + (size_t)s1 * HH);
                        float4 v2 = *(const float4*)(hp + (size_t)s2 * HH);
                        float4 v3 = *(const float4*)(hp + (size_t)s3 * HH);
                        acc.x += (v0.x + v1.x) + (v2.x + v3.x);
                        acc.y += (v0.y + v1.y) + (v2.y + v3.y);
                        acc.z += (v0.z + v1.z) + (v2.z + v3.z);
                        acc.w += (v0.w + v1.w) + (v2.w + v3.w);
                    }
                    for (; p < e; ++p) {
                        int s = g_csr[p];
                        float4 v = *(const float4*)(hp + (size_t)s * HH);
                        acc.x += v.x; acc.y += v.y; acc.z += v.z; acc.w += v.w;
                    }
                }
                *(float4*)&AggT[r * PAD + lane * 4] = acc;
            }
        }
        __syncthreads();

        unsigned long long acc[8][4];
#pragma unroll
        for (int i = 0; i < 8; i++)
#pragma unroll
            for (int j = 0; j < 4; j++) acc[i][j] = 0ull;

        for (int k0 = 0; k0 < HH; k0 += 16) {
            float4 a0 = *(const float4*)&AggT[lr * PAD + k0 + lk];
            float4 a1 = *(const float4*)&AggT[lr * PAD + k0 + lk + 4];
            As[lk + 0][lr] = a0.x; As[lk + 1][lr] = a0.y;
            As[lk + 2][lr] = a0.z; As[lk + 3][lr] = a0.w;
            As[lk + 4][lr] = a1.x; As[lk + 5][lr] = a1.y;
            As[lk + 6][lr] = a1.z; As[lk + 7][lr] = a1.w;

            *(float4*)&Ws[wr][wc]     = *(const float4*)(Wa + (size_t)(k0 + wr) * HH + wc);
            *(float4*)&Ws[wr + 8][wc] = *(const float4*)(Wa + (size_t)(k0 + wr + 8) * HH + wc);
            __syncthreads();

#pragma unroll
            for (int kk = 0; kk < 16; kk++) {
                float4 av0 = *(const float4*)&As[kk][tm];
                float4 av1 = *(const float4*)&As[kk][tm + 4];
                ulonglong2 wv0 = *(const ulonglong2*)&Ws[kk][tn];
                ulonglong2 wv1 = *(const ulonglong2*)&Ws[kk][tn + 4];
                unsigned long long wp[4] = {wv0.x, wv0.y, wv1.x, wv1.y};
                float aa[8] = {av0.x, av0.y, av0.z, av0.w, av1.x, av1.y, av1.z, av1.w};
                unsigned long long ap[8];
#pragma unroll
                for (int i = 0; i < 8; i++) ap[i] = pack2(aa[i], aa[i]);
#pragma unroll
                for (int i = 0; i < 8; i++)
#pragma unroll
                    for (int j = 0; j < 4; j++)
                        acc[i][j] = fma2(ap[i], wp[j], acc[i][j]);
            }
            __syncthreads();
        }

        float4 b0 = *(const float4*)(ba + tn);
        float4 b1 = *(const float4*)(ba + tn + 4);
        float bv[8] = {b0.x, b0.y, b0.z, b0.w, b1.x, b1.y, b1.z, b1.w};
#pragma unroll
        for (int i = 0; i < 8; i++)
#pragma unroll
            for (int j = 0; j < 4; j++) {
                float2 f = unpack2(acc[i][j]);
                o1[i][2 * j]     = fmaxf(f.x + bv[2 * j], 0.f);
                o1[i][2 * j + 1] = fmaxf(f.y + bv[2 * j + 1], 0.f);
            }
    }

    // Store H1 tile to smem, k-major + XOR swizzle (overwrites AggT region).
#pragma unroll
    for (int c = 0; c < 8; c++) {
        int col = tn + c;
        int sw = (col >> 3) & 31;
        float* base = H1t + col * 128;
        *(float4*)&base[(((tm >> 2) ^ sw) << 2)] =
            make_float4(o1[0][c], o1[1][c], o1[2][c], o1[3][c]);
        *(float4*)&base[((((tm >> 2) + 1) ^ sw) << 2)] =
            make_float4(o1[4][c], o1[5][c], o1[6][c], o1[7][c]);
    }
    __syncthreads();

    // ---- phase 2 ----
    unsigned long long acc[8][4];
#pragma unroll
    for (int i = 0; i < 8; i++)
#pragma unroll
        for (int j = 0; j < 4; j++) acc[i][j] = 0ull;

    const int slot0 = tm >> 2;
    for (int k0 = 0; k0 < HH; k0 += 16) {
        *(float4*)&Ws[wr][wc]     = *(const float4*)(Wb + (size_t)(k0 + wr) * HH + wc);
        *(float4*)&Ws[wr + 8][wc] = *(const float4*)(Wb + (size_t)(k0 + wr + 8) * HH + wc);
        __syncthreads();

#pragma unroll
        for (int kk = 0; kk < 16; kk++) {
            int k = k0 + kk;
            int sw = (k >> 3) & 31;
            const float* hrow = H1t + k * 128;
            float4 av0 = *(const float4*)&hrow[((slot0 ^ sw) << 2)];
            float4 av1 = *(const float4*)&hrow[(((slot0 + 1) ^ sw) << 2)];
            ulonglong2 wv0 = *(const ulonglong2*)&Ws[kk][tn];
            ulonglong2 wv1 = *(const ulonglong2*)&Ws[kk][tn + 4];
            unsigned long long wp[4] = {wv0.x, wv0.y, wv1.x, wv1.y};
            float aa[8] = {av0.x, av0.y, av0.z, av0.w, av1.x, av1.y, av1.z, av1.w};
            unsigned long long ap[8];
#pragma unroll
            for (int i = 0; i < 8; i++) ap[i] = pack2(aa[i], aa[i]);
#pragma unroll
            for (int i = 0; i < 8; i++)
#pragma unroll
                for (int j = 0; j < 4; j++)
                    acc[i][j] = fma2(ap[i], wp[j], acc[i][j]);
        }
        __syncthreads();
    }

    float4 b0 = *(const float4*)(bb + tn);
    float4 b1 = *(const float4*)(bb + tn + 4);
    float bv[8] = {b0.x, b0.y, b0.z, b0.w, b1.x, b1.y, b1.z, b1.w};
#pragma unroll
    for (int i = 0; i < 8; i++) {
        int row = rowBase + tm + i;
        if (row < NN) {
            float o[8];
#pragma unroll
            for (int j = 0; j < 4; j++) {
                float2 f = unpack2(acc[i][j]);
                o[2 * j]     = fmaxf(f.x + bv[2 * j], 0.f);
                o[2 * j + 1] = fmaxf(f.y + bv[2 * j + 1], 0.f);
            }
            if (POOL) {
                float* po = poolOut + (size_t)seg[row] * HH + tn;
#pragma unroll
                for (int c = 0; c < 8; c++) atomicAdd(po + c, o[c]);
            } else {
                *(float4*)(C + (size_t)row * HH + tn)     = make_float4(o[0], o[1], o[2], o[3]);
                *(float4*)(C + (size_t)row * HH + tn + 4) = make_float4(o[4], o[5], o[6], o[7]);
            }
        }
    }
}

// ---------------------------------------------------------------------------
__global__ void pool_scatter(const float* __restrict__ h, const int* __restrict__ seg,
                             float* __restrict__ out, int n) {
    unsigned t = blockIdx.x * blockDim.x + threadIdx.x;
    unsigned i = t >> 5;
    if (i >= (unsigned)n) return;
    int lane = (int)(t & 31);
    int sg = seg[i];
    float4 v = *(const float4*)(h + (size_t)i * HH + lane * 4);
    float* o = out + (size_t)sg * HH + lane * 4;
    atomicAdd(o + 0, v.x);
    atomicAdd(o + 1, v.y);
    atomicAdd(o + 2, v.z);
    atomicAdd(o + 3, v.w);
}

__global__ void head(const float* __restrict__ graph, const float* __restrict__ l1W,
                     const float* __restrict__ l1b, const float* __restrict__ l2W,
                     const float* __restrict__ l2b, float* __restrict__ out) {
    __shared__ float row[HH];
    __shared__ float h1[HH];
    __shared__ float red[HH];
    int g = blockIdx.x;
    int j = threadIdx.x;

    row[j] = graph[g * HH + j];
    __syncthreads();

    float acc = l1b[j];
#pragma unroll 8
    for (int k = 0; k < HH; k++) acc = fmaf(row[k], l1W[k * HH + j], acc);
    h1[j] = fmaxf(acc, 0.f);
    __syncthreads();

    float acc2 = l2b[j];
#pragma unroll 8
    for (int k = 0; k < HH; k++) acc2 = fmaf(h1[k], l2W[k * HH + j], acc2);

    red[j] = acc2;
    __syncthreads();
    for (int s = 64; s > 0; s >>= 1) {
        if (j < s) red[j] = fmaxf(red[j], red[j + s]);
        __syncthreads();
    }
    float m = red[0];
    __syncthreads();
    red[j] = expf(acc2 - m);
    __syncthreads();
    for (int s = 64; s > 0; s >>= 1) {
        if (j < s) red[j] += red[j + s];
        __syncthreads();
    }
    float lse = m + logf(red[0]);
    out[g * HH + j] = acc2 - lse;
}

// ---------------------------------------------------------------------------
extern "C" void kernel_launch(void* const* d_in, const int* in_sizes, int n_in,
                              void* d_out, int out_size) {
    const float* x   = (const float*)d_in[0];
    const int*   ei  = (const int*)  d_in[1];
    const int*   n2s = (const int*)  d_in[2];
    const int*   s2g = (const int*)  d_in[3];
    const float* W1a = (const float*)d_in[4];
    const float* b1a = (const float*)d_in[5];
    const float* W1b = (const float*)d_in[6];
    const float* b1b = (const float*)d_in[7];
    const float* cWa = (const float*)d_in[8];
    const float* cba = (const float*)d_in[9];
    const float* cWb = (const float*)d_in[10];
    const float* cbb = (const float*)d_in[11];
    const float* l1W = (const float*)d_in[12];
    const float* l1b = (const float*)d_in[13];
    const float* l2W = (const float*)d_in[14];
    const float* l2b = (const float*)d_in[15];
    float* out = (float*)d_out;

    const int* src = ei;
    const int* dst = ei + EE;

    float *ph, *ph2, *ppool;
    int *prp, *pbs, *pcur;
    cudaGetSymbolAddress((void**)&ph,    g_h);
    cudaGetSymbolAddress((void**)&ph2,   g_h2);
    cudaGetSymbolAddress((void**)&ppool, g_pool);
    cudaGetSymbolAddress((void**)&prp,   g_rowptr);
    cudaGetSymbolAddress((void**)&pbs,   g_bsum);
    cudaGetSymbolAddress((void**)&pcur,  g_cur);

    float* psub = ppool;
    float* pgr  = ppool + SS * HH;

    const int TB = 256;
    const int gemmBlocks = (NN + 127) / 128;
    const int nScan = NN + 1;
    const int scanBlocks = (nScan + 1023) / 1024;
    const int initN = (SS + GG) * HH / 4;
    const int SMEM = (128 * PAD + 2048 + 2048) * 4;  // ~84KB

    cudaFuncSetAttribute(gin_conv<true,  false>, cudaFuncAttributeMaxDynamicSharedMemorySize, SMEM);
    cudaFuncSetAttribute(gin_conv<false, false>, cudaFuncAttributeMaxDynamicSharedMemorySize, SMEM);
    cudaFuncSetAttribute(gin_conv<false, true>,  cudaFuncAttributeMaxDynamicSharedMemorySize, SMEM);

    // ---- init + CSR build ----
    init_zero<<<(initN + TB - 1) / TB, TB>>>(prp, (float4*)ppool);
    hist_dst<<<(EE + TB - 1) / TB, TB>>>(dst);
    scan1<<<scanBlocks, 1024>>>(prp, pbs, nScan);
    scan_finish<<<scanBlocks, 1024>>>(prp, pbs, pcur, nScan);
    fill_csr<<<(EE + TB - 1) / TB, TB>>>(src, dst);

    // ---- conv1 (gather fused, F_IN=2): x -> ph ----
    gin_conv<true, false><<<gemmBlocks, TB, SMEM>>>(x, W1a, b1a, W1b, b1b, ph, nullptr, nullptr);

    // ---- convs 2..3 (gather fused), ping-pong ph <-> ph2 ----
    gin_conv<false, false><<<gemmBlocks, TB, SMEM>>>(ph,  cWa, cba, cWb, cbb, ph2, nullptr, nullptr);
    gin_conv<false, false><<<gemmBlocks, TB, SMEM>>>(ph2, cWa + HH * HH, cba + HH,
                                                     cWb + HH * HH, cbb + HH, ph, nullptr, nullptr);

    // ---- conv 4 (gather + node->subgraph pooling fused): ph -> psub ----
    gin_conv<false, true><<<gemmBlocks, TB, SMEM>>>(ph, cWa + 2 * HH * HH, cba + 2 * HH,
                                                    cWb + 2 * HH * HH, cbb + 2 * HH,
                                                    nullptr, n2s, psub);

    // ---- subgraph -> graph pooling ----
    pool_scatter<<<(SS * 32 + TB - 1) / TB, TB>>>(psub, s2g, pgr, SS);

    // ---- head ----
    head<<<GG, HH>>>(pgr, l1W, l1b, l2W, l2b, out);
}

// round 6
// speedup vs baseline: 1.1803x; 1.1803x over previous
#include <cuda_runtime.h>
#include <math.h>

#define NN 50000
#define EE 800000
#define HH 128
#define SS 5000
#define GG 64

// Scratch (device globals: no allocation allowed)
__device__ float g_h   [NN*HH];
__device__ float g_aggr[NN*HH];
__device__ float g_pool[(SS+GG)*HH];
__device__ int   g_rowptr[NN+1];
__device__ int   g_cur[NN];
__device__ int   g_csr[EE];
__device__ int   g_bsum[64];

// ---------------------------------------------------------------------------
// packed f32x2 helpers
__device__ __forceinline__ unsigned long long pack2(float lo, float hi) {
    unsigned long long r;
    asm("mov.b64 %0, {%1, %2};" : "=l"(r) : "f"(lo), "f"(hi));
    return r;
}
__device__ __forceinline__ unsigned long long fma2(unsigned long long a,
                                                   unsigned long long b,
                                                   unsigned long long c) {
    unsigned long long d;
    asm("fma.rn.f32x2 %0, %1, %2, %3;" : "=l"(d) : "l"(a), "l"(b), "l"(c));
    return d;
}
__device__ __forceinline__ float2 unpack2(unsigned long long v) {
    float2 f;
    asm("mov.b64 {%0, %1}, %2;" : "=f"(f.x), "=f"(f.y) : "l"(v));
    return f;
}

// ---------------------------------------------------------------------------
__global__ void init_zero(int* __restrict__ rowptr, float4* __restrict__ pool) {
    int i = blockIdx.x * blockDim.x + threadIdx.x;
    if (i < NN + 1) rowptr[i] = 0;
    if (i < (SS + GG) * HH / 4) pool[i] = make_float4(0.f, 0.f, 0.f, 0.f);
}

__global__ void hist_dst(const int* __restrict__ dst) {
    int e = blockIdx.x * blockDim.x + threadIdx.x;
    if (e < EE) atomicAdd(&g_rowptr[dst[e] + 1], 1);
}

__global__ void scan1(int* __restrict__ data, int* __restrict__ bsum, int n) {
    __shared__ int sh[1024];
    int gid = blockIdx.x * 1024 + threadIdx.x;
    int v = (gid < n) ? data[gid] : 0;
    sh[threadIdx.x] = v;
    __syncthreads();
    for (int off = 1; off < 1024; off <<= 1) {
        int t = (threadIdx.x >= off) ? sh[threadIdx.x - off] : 0;
        __syncthreads();
        sh[threadIdx.x] += t;
        __syncthreads();
    }
    if (gid < n) data[gid] = sh[threadIdx.x];
    if (threadIdx.x == 1023) bsum[blockIdx.x] = sh[1023];
}

__global__ void scan_finish(int* __restrict__ data, const int* __restrict__ bsum,
                            int* __restrict__ cur, int n) {
    __shared__ int offs;
    if (threadIdx.x == 0) {
        int s = 0;
        for (int j = 0; j < blockIdx.x; j++) s += bsum[j];
        offs = s;
    }
    __syncthreads();
    int gid = blockIdx.x * 1024 + threadIdx.x;
    if (gid < n) {
        int v = data[gid] + offs;
        data[gid] = v;
        if (gid < NN) cur[gid] = v;
    }
}

__global__ void fill_csr(const int* __restrict__ src, const int* __restrict__ dst) {
    int e = blockIdx.x * blockDim.x + threadIdx.x;
    if (e >= EE) return;
    int d = dst[e];
    int pos = atomicAdd(&g_cur[d], 1);
    g_csr[pos] = src[e];
}

// ---------------------------------------------------------------------------
// conv1 aggregation (F_IN=2) via CSR gather: one thread per node
__global__ void aggr2_csr(const float* __restrict__ x, float* __restrict__ out) {
    int n = blockIdx.x * blockDim.x + threadIdx.x;
    if (n >= NN) return;
    float2 acc = *(const float2*)(x + 2 * n);
    int p = g_rowptr[n], e = g_rowptr[n + 1];
    for (; p < e; ++p) {
        int s = g_csr[p];
        float2 v = *(const float2*)(x + 2 * s);
        acc.x += v.x; acc.y += v.y;
    }
    *(float2*)(out + 2 * n) = acc;
}

// H=128 aggregation via CSR gather: one warp per node, 4 floats per lane.
__global__ void aggr128_csr(const float* __restrict__ h, float* __restrict__ out) {
    unsigned t = blockIdx.x * blockDim.x + threadIdx.x;
    unsigned n = t >> 5;
    if (n >= NN) return;
    int lane = (int)(t & 31);
    const float* hp = h + lane * 4;
    float4 acc = *(const float4*)(hp + (size_t)n * HH);
    int p = g_rowptr[n], e = g_rowptr[n + 1];
    for (; p + 3 < e; p += 4) {
        int s0 = g_csr[p], s1 = g_csr[p + 1], s2 = g_csr[p + 2], s3 = g_csr[p + 3];
        float4 v0 = *(const float4*)(hp + (size_t)s0 * HH);
        float4 v1 = *(const float4*)(hp + (size_t)s1 * HH);
        float4 v2 = *(const float4*)(hp + (size_t)s2 * HH);
        float4 v3 = *(const float4*)(hp + (size_t)s3 * HH);
        acc.x += (v0.x + v1.x) + (v2.x + v3.x);
        acc.y += (v0.y + v1.y) + (v2.y + v3.y);
        acc.z += (v0.z + v1.z) + (v2.z + v3.z);
        acc.w += (v0.w + v1.w) + (v2.w + v3.w);
    }
    for (; p < e; ++p) {
        int s = g_csr[p];
        float4 v = *(const float4*)(hp + (size_t)s * HH);
        acc.x += v.x; acc.y += v.y; acc.z += v.z; acc.w += v.w;
    }
    *(float4*)(out + (size_t)n * HH + lane * 4) = acc;
}

// ---------------------------------------------------------------------------
// Fused GIN MLP: C = relu(relu(A @ Wa + ba) @ Wb + bb)
// 256 threads, 128-row tile, thread = 8x8. Round-4 proven structure.
// POOL: epilogue atomicAdds rows into poolOut[seg[row]] instead of writing C.
template<bool CONV1, bool POOL>
__global__ void __launch_bounds__(256, 2)
gin_mlp(const float* __restrict__ A, const float* __restrict__ Wa,
        const float* __restrict__ ba, const float* __restrict__ Wb,
        const float* __restrict__ bb, float* __restrict__ C,
        const int* __restrict__ seg, float* __restrict__ poolOut) {
    extern __shared__ float sm[];
    float* H1t = sm;                                   // 16384 floats (64KB)
    float (*As)[128] = (float(*)[128])(sm + 16384);    // [16][128]
    float (*Ws)[128] = (float(*)[128])(sm + 16384 + 2048);

    const int tid = threadIdx.x;
    const int tm = (tid >> 4) * 8;   // row offset in tile
    const int tn = (tid & 15) * 8;   // col offset
    const int rowBase = blockIdx.x * 128;

    const int lr = tid >> 1;          // A row to load
    const int lk = (tid & 1) * 8;     // k offset 0 or 8
    const int wr = tid >> 5;          // W row
    const int wc = (tid & 31) * 4;    // W col

    float o1[8][8];  // phase-1 output block

    if (CONV1) {
        float4 wa0 = *(const float4*)(Wa + tn);
        float4 wa1 = *(const float4*)(Wa + tn + 4);
        float4 wb0 = *(const float4*)(Wa + HH + tn);
        float4 wb1 = *(const float4*)(Wa + HH + tn + 4);
        float4 b0  = *(const float4*)(ba + tn);
        float4 b1  = *(const float4*)(ba + tn + 4);
        float w0v[8] = {wa0.x, wa0.y, wa0.z, wa0.w, wa1.x, wa1.y, wa1.z, wa1.w};
        float w1v[8] = {wb0.x, wb0.y, wb0.z, wb0.w, wb1.x, wb1.y, wb1.z, wb1.w};
        float bv[8]  = {b0.x, b0.y, b0.z, b0.w, b1.x, b1.y, b1.z, b1.w};
#pragma unroll
        for (int i = 0; i < 8; i++) {
            int row = rowBase + tm + i;
            float a0 = 0.f, a1 = 0.f;
            if (row < NN) {
                float2 a = *(const float2*)(A + 2 * (size_t)row);
                a0 = a.x; a1 = a.y;
            }
#pragma unroll
            for (int c = 0; c < 8; c++)
                o1[i][c] = fmaxf(fmaf(a0, w0v[c], fmaf(a1, w1v[c], bv[c])), 0.f);
        }
    } else {
        const bool rowOK = (rowBase + lr) < NN;
        const float* Arow = A + (size_t)(rowBase + lr) * HH;

        unsigned long long acc[8][4];
#pragma unroll
        for (int i = 0; i < 8; i++)
#pragma unroll
            for (int j = 0; j < 4; j++) acc[i][j] = 0ull;

        for (int k0 = 0; k0 < HH; k0 += 16) {
            float4 a0 = make_float4(0.f, 0.f, 0.f, 0.f), a1 = a0;
            if (rowOK) {
                a0 = *(const float4*)(Arow + k0 + lk);
                a1 = *(const float4*)(Arow + k0 + lk + 4);
            }
            As[lk + 0][lr] = a0.x; As[lk + 1][lr] = a0.y;
            As[lk + 2][lr] = a0.z; As[lk + 3][lr] = a0.w;
            As[lk + 4][lr] = a1.x; As[lk + 5][lr] = a1.y;
            As[lk + 6][lr] = a1.z; As[lk + 7][lr] = a1.w;

            *(float4*)&Ws[wr][wc]     = *(const float4*)(Wa + (size_t)(k0 + wr) * HH + wc);
            *(float4*)&Ws[wr + 8][wc] = *(const float4*)(Wa + (size_t)(k0 + wr + 8) * HH + wc);
            __syncthreads();

#pragma unroll
            for (int kk = 0; kk < 16; kk++) {
                float4 av0 = *(const float4*)&As[kk][tm];
                float4 av1 = *(const float4*)&As[kk][tm + 4];
                ulonglong2 wv0 = *(const ulonglong2*)&Ws[kk][tn];
                ulonglong2 wv1 = *(const ulonglong2*)&Ws[kk][tn + 4];
                unsigned long long wp[4] = {wv0.x, wv0.y, wv1.x, wv1.y};
                float aa[8] = {av0.x, av0.y, av0.z, av0.w, av1.x, av1.y, av1.z, av1.w};
                unsigned long long ap[8];
#pragma unroll
                for (int i = 0; i < 8; i++) ap[i] = pack2(aa[i], aa[i]);
#pragma unroll
                for (int i = 0; i < 8; i++)
#pragma unroll
                    for (int j = 0; j < 4; j++)
                        acc[i][j] = fma2(ap[i], wp[j], acc[i][j]);
            }
            __syncthreads();
        }

        float4 b0 = *(const float4*)(ba + tn);
        float4 b1 = *(const float4*)(ba + tn + 4);
        float bv[8] = {b0.x, b0.y, b0.z, b0.w, b1.x, b1.y, b1.z, b1.w};
#pragma unroll
        for (int i = 0; i < 8; i++)
#pragma unroll
            for (int j = 0; j < 4; j++) {
                float2 f = unpack2(acc[i][j]);
                o1[i][2 * j]     = fmaxf(f.x + bv[2 * j], 0.f);
                o1[i][2 * j + 1] = fmaxf(f.y + bv[2 * j + 1], 0.f);
            }
    }

    // Store H1 tile to smem, k-major + XOR swizzle.
#pragma unroll
    for (int c = 0; c < 8; c++) {
        int col = tn + c;
        int sw = (col >> 3) & 31;
        float* base = H1t + col * 128;
        *(float4*)&base[(((tm >> 2) ^ sw) << 2)] =
            make_float4(o1[0][c], o1[1][c], o1[2][c], o1[3][c]);
        *(float4*)&base[((((tm >> 2) + 1) ^ sw) << 2)] =
            make_float4(o1[4][c], o1[5][c], o1[6][c], o1[7][c]);
    }
    __syncthreads();

    // ---- phase 2: relu(H1 @ Wb + bb) ----
    unsigned long long acc[8][4];
#pragma unroll
    for (int i = 0; i < 8; i++)
#pragma unroll
        for (int j = 0; j < 4; j++) acc[i][j] = 0ull;

    const int slot0 = tm >> 2;
    for (int k0 = 0; k0 < HH; k0 += 16) {
        *(float4*)&Ws[wr][wc]     = *(const float4*)(Wb + (size_t)(k0 + wr) * HH + wc);
        *(float4*)&Ws[wr + 8][wc] = *(const float4*)(Wb + (size_t)(k0 + wr + 8) * HH + wc);
        __syncthreads();

#pragma unroll
        for (int kk = 0; kk < 16; kk++) {
            int k = k0 + kk;
            int sw = (k >> 3) & 31;
            const float* hrow = H1t + k * 128;
            float4 av0 = *(const float4*)&hrow[((slot0 ^ sw) << 2)];
            float4 av1 = *(const float4*)&hrow[(((slot0 + 1) ^ sw) << 2)];
            ulonglong2 wv0 = *(const ulonglong2*)&Ws[kk][tn];
            ulonglong2 wv1 = *(const ulonglong2*)&Ws[kk][tn + 4];
            unsigned long long wp[4] = {wv0.x, wv0.y, wv1.x, wv1.y};
            float aa[8] = {av0.x, av0.y, av0.z, av0.w, av1.x, av1.y, av1.z, av1.w};
            unsigned long long ap[8];
#pragma unroll
            for (int i = 0; i < 8; i++) ap[i] = pack2(aa[i], aa[i]);
#pragma unroll
            for (int i = 0; i < 8; i++)
#pragma unroll
                for (int j = 0; j < 4; j++)
                    acc[i][j] = fma2(ap[i], wp[j], acc[i][j]);
        }
        __syncthreads();
    }

    float4 b0 = *(const float4*)(bb + tn);
    float4 b1 = *(const float4*)(bb + tn + 4);
    float bv[8] = {b0.x, b0.y, b0.z, b0.w, b1.x, b1.y, b1.z, b1.w};
#pragma unroll
    for (int i = 0; i < 8; i++) {
        int row = rowBase + tm + i;
        if (row < NN) {
            float o[8];
#pragma unroll
            for (int j = 0; j < 4; j++) {
                float2 f = unpack2(acc[i][j]);
                o[2 * j]     = fmaxf(f.x + bv[2 * j], 0.f);
                o[2 * j + 1] = fmaxf(f.y + bv[2 * j + 1], 0.f);
            }
            if (POOL) {
                float* po = poolOut + (size_t)seg[row] * HH + tn;
#pragma unroll
                for (int c = 0; c < 8; c++) atomicAdd(po + c, o[c]);
            } else {
                *(float4*)(C + (size_t)row * HH + tn)     = make_float4(o[0], o[1], o[2], o[3]);
                *(float4*)(C + (size_t)row * HH + tn + 4) = make_float4(o[4], o[5], o[6], o[7]);
            }
        }
    }
}

// ---------------------------------------------------------------------------
// Segment-sum scatter (subgraph -> graph): one warp per row.
__global__ void pool_scatter(const float* __restrict__ h, const int* __restrict__ seg,
                             float* __restrict__ out, int n) {
    unsigned t = blockIdx.x * blockDim.x + threadIdx.x;
    unsigned i = t >> 5;
    if (i >= (unsigned)n) return;
    int lane = (int)(t & 31);
    int sg = seg[i];
    float4 v = *(const float4*)(h + (size_t)i * HH + lane * 4);
    float* o = out + (size_t)sg * HH + lane * 4;
    atomicAdd(o + 0, v.x);
    atomicAdd(o + 1, v.y);
    atomicAdd(o + 2, v.z);
    atomicAdd(o + 3, v.w);
}

// Head: per-graph MLP + log_softmax.
__global__ void head(const float* __restrict__ graph, const float* __restrict__ l1W,
                     const float* __restrict__ l1b, const float* __restrict__ l2W,
                     const float* __restrict__ l2b, float* __restrict__ out) {
    __shared__ float row[HH];
    __shared__ float h1[HH];
    __shared__ float red[HH];
    int g = blockIdx.x;
    int j = threadIdx.x;

    row[j] = graph[g * HH + j];
    __syncthreads();

    float acc = l1b[j];
#pragma unroll 8
    for (int k = 0; k < HH; k++) acc = fmaf(row[k], l1W[k * HH + j], acc);
    h1[j] = fmaxf(acc, 0.f);
    __syncthreads();

    float acc2 = l2b[j];
#pragma unroll 8
    for (int k = 0; k < HH; k++) acc2 = fmaf(h1[k], l2W[k * HH + j], acc2);

    red[j] = acc2;
    __syncthreads();
    for (int s = 64; s > 0; s >>= 1) {
        if (j < s) red[j] = fmaxf(red[j], red[j + s]);
        __syncthreads();
    }
    float m = red[0];
    __syncthreads();
    red[j] = expf(acc2 - m);
    __syncthreads();
    for (int s = 64; s > 0; s >>= 1) {
        if (j < s) red[j] += red[j + s];
        __syncthreads();
    }
    float lse = m + logf(red[0]);
    out[g * HH + j] = acc2 - lse;
}

// ---------------------------------------------------------------------------
extern "C" void kernel_launch(void* const* d_in, const int* in_sizes, int n_in,
                              void* d_out, int out_size) {
    const float* x   = (const float*)d_in[0];
    const int*   ei  = (const int*)  d_in[1];
    const int*   n2s = (const int*)  d_in[2];
    const int*   s2g = (const int*)  d_in[3];
    const float* W1a = (const float*)d_in[4];
    const float* b1a = (const float*)d_in[5];
    const float* W1b = (const float*)d_in[6];
    const float* b1b = (const float*)d_in[7];
    const float* cWa = (const float*)d_in[8];
    const float* cba = (const float*)d_in[9];
    const float* cWb = (const float*)d_in[10];
    const float* cbb = (const float*)d_in[11];
    const float* l1W = (const float*)d_in[12];
    const float* l1b = (const float*)d_in[13];
    const float* l2W = (const float*)d_in[14];
    const float* l2b = (const float*)d_in[15];
    float* out = (float*)d_out;

    const int* src = ei;
    const int* dst = ei + EE;

    float *ph, *pag, *ppool;
    int *prp, *pbs, *pcur;
    cudaGetSymbolAddress((void**)&ph,    g_h);
    cudaGetSymbolAddress((void**)&pag,   g_aggr);
    cudaGetSymbolAddress((void**)&ppool, g_pool);
    cudaGetSymbolAddress((void**)&prp,   g_rowptr);
    cudaGetSymbolAddress((void**)&pbs,   g_bsum);
    cudaGetSymbolAddress((void**)&pcur,  g_cur);

    float* psub = ppool;
    float* pgr  = ppool + SS * HH;

    const int TB = 256;
    const int gemmBlocks = (NN + 127) / 128;
    const int nScan = NN + 1;
    const int scanBlocks = (nScan + 1023) / 1024;
    const int initN = (SS + GG) * HH / 4;
    const int SMEM = (16384 + 2048 + 2048) * 4;  // 80KB

    cudaFuncSetAttribute(gin_mlp<true,  false>, cudaFuncAttributeMaxDynamicSharedMemorySize, SMEM);
    cudaFuncSetAttribute(gin_mlp<false, false>, cudaFuncAttributeMaxDynamicSharedMemorySize, SMEM);
    cudaFuncSetAttribute(gin_mlp<false, true>,  cudaFuncAttributeMaxDynamicSharedMemorySize, SMEM);

    // ---- init + CSR build ----
    init_zero<<<(initN + TB - 1) / TB, TB>>>(prp, (float4*)ppool);
    hist_dst<<<(EE + TB - 1) / TB, TB>>>(dst);
    scan1<<<scanBlocks, 1024>>>(prp, pbs, nScan);
    scan_finish<<<scanBlocks, 1024>>>(prp, pbs, pcur, nScan);
    fill_csr<<<(EE + TB - 1) / TB, TB>>>(src, dst);

    // ---- conv1 ----
    aggr2_csr<<<(NN + TB - 1) / TB, TB>>>(x, pag);
    gin_mlp<true, false><<<gemmBlocks, TB, SMEM>>>(pag, W1a, b1a, W1b, b1b, ph, nullptr, nullptr);

    // ---- convs 2..3 ----
    for (int i = 0; i < 2; i++) {
        aggr128_csr<<<(NN * 32 + TB - 1) / TB, TB>>>(ph, pag);
        gin_mlp<false, false><<<gemmBlocks, TB, SMEM>>>(pag, cWa + i * HH * HH, cba + i * HH,
                                                        cWb + i * HH * HH, cbb + i * HH,
                                                        ph, nullptr, nullptr);
    }

    // ---- conv 4: node->subgraph pooling fused into epilogue ----
    aggr128_csr<<<(NN * 32 + TB - 1) / TB, TB>>>(ph, pag);
    gin_mlp<false, true><<<gemmBlocks, TB, SMEM>>>(pag, cWa + 2 * HH * HH, cba + 2 * HH,
                                                   cWb + 2 * HH * HH, cbb + 2 * HH,
                                                   nullptr, n2s, psub);

    // ---- subgraph -> graph pooling ----
    pool_scatter<<<(SS * 32 + TB - 1) / TB, TB>>>(psub, s2g, pgr, SS);

    // ---- head ----
    head<<<GG, HH>>>(pgr, l1W, l1b, l2W, l2b, out);
}

// round 8
// speedup vs baseline: 1.5612x; 1.3227x over previous
#include <cuda_runtime.h>
#include <cuda_bf16.h>
#include <math.h>

#define NN 50000
#define EE 800000
#define HH 128
#define SS 5000
#define GG 64
#define NTILES 391   // ceil(NN/128)

// Scratch (device globals: no allocation allowed)
__device__ float g_h    [NN*HH];
__device__ float g_aggr2[NN*2];
__device__ float g_pool [(SS+GG)*HH];
__device__ __nv_bfloat16 g_ahi[NTILES*16384];  // per-tile LDSM-layout A hi
__device__ __nv_bfloat16 g_alo[NTILES*16384];
__device__ __nv_bfloat16 g_whi[7*16384];       // weights, [n][k] LDSM layout
__device__ __nv_bfloat16 g_wlo[7*16384];
__device__ int   g_rowptr[NN+1];
__device__ int   g_cur[NN];
__device__ int   g_csr[EE];
__device__ int   g_bsum[64];

// ---------------------------------------------------------------------------
// LDSM-friendly swizzled layout: 128 rows x 256 bytes (128 bf16). 16B chunks
// XOR-swizzled by row&7 -> ldmatrix reads of 8 rows are bank-conflict-free.
__device__ __host__ __forceinline__ int ls_off(int row, int kbyte) {
    return row * 256 + ((((kbyte >> 4) ^ row) & 7) << 4) + (kbyte & 15) + (kbyte & ~127);
}
// NOTE: kbyte < 256 always here, and chunk index = kbyte>>4 in [0,16): the
// swizzle must only permute chunks within the row. (kbyte & ~127) term keeps
// chunks 8..15 in the upper half: chunk = (kbyte>>4), swizzle XORs low 3 bits.

__device__ __forceinline__ unsigned bfpair(float f0, float f1) {  // {lo:f0, hi:f1}
    unsigned r;
    asm("cvt.rn.bf16x2.f32 %0, %1, %2;" : "=r"(r) : "f"(f1), "f"(f0));
    return r;
}

__device__ __forceinline__ void ldsm4(unsigned& r0, unsigned& r1, unsigned& r2,
                                      unsigned& r3, unsigned addr) {
    asm volatile("ldmatrix.sync.aligned.m8n8.x4.shared.b16 {%0,%1,%2,%3}, [%4];"
                 : "=r"(r0), "=r"(r1), "=r"(r2), "=r"(r3) : "r"(addr));
}

__device__ __forceinline__ void mma16816(float* c, unsigned a0, unsigned a1,
                                         unsigned a2, unsigned a3,
                                         unsigned b0, unsigned b1) {
    asm volatile("mma.sync.aligned.m16n8k16.row.col.f32.bf16.bf16.f32 "
                 "{%0,%1,%2,%3}, {%4,%5,%6,%7}, {%8,%9}, {%0,%1,%2,%3};"
                 : "+f"(c[0]), "+f"(c[1]), "+f"(c[2]), "+f"(c[3])
                 : "r"(a0), "r"(a1), "r"(a2), "r"(a3), "r"(b0), "r"(b1));
}

__device__ __forceinline__ void split_store(unsigned AHI, unsigned ALO,
                                            int row, int col, float f0, float f1) {
    unsigned hp = bfpair(f0, f1);
    float r0 = f0 - __uint_as_float(hp << 16);
    float r1 = f1 - __uint_as_float(hp & 0xFFFF0000u);
    unsigned lp = bfpair(r0, r1);
    int off = ls_off(row, col * 2);
    asm volatile("st.shared.b32 [%0], %1;" :: "r"(AHI + off), "r"(hp) : "memory");
    asm volatile("st.shared.b32 [%0], %1;" :: "r"(ALO + off), "r"(lp) : "memory");
}

// ---------------------------------------------------------------------------
__global__ void init_zero(int* __restrict__ rowptr, float4* __restrict__ pool) {
    int i = blockIdx.x * blockDim.x + threadIdx.x;
    if (i < NN + 1) rowptr[i] = 0;
    if (i < (SS + GG) * HH / 4) pool[i] = make_float4(0.f, 0.f, 0.f, 0.f);
}

__global__ void hist_dst(const int* __restrict__ dst) {
    int e = blockIdx.x * blockDim.x + threadIdx.x;
    if (e < EE) atomicAdd(&g_rowptr[dst[e] + 1], 1);
}

__global__ void scan1(int* __restrict__ data, int* __restrict__ bsum, int n) {
    __shared__ int sh[1024];
    int gid = blockIdx.x * 1024 + threadIdx.x;
    int v = (gid < n) ? data[gid] : 0;
    sh[threadIdx.x] = v;
    __syncthreads();
    for (int off = 1; off < 1024; off <<= 1) {
        int t = (threadIdx.x >= off) ? sh[threadIdx.x - off] : 0;
        __syncthreads();
        sh[threadIdx.x] += t;
        __syncthreads();
    }
    if (gid < n) data[gid] = sh[threadIdx.x];
    if (threadIdx.x == 1023) bsum[blockIdx.x] = sh[1023];
}

__global__ void scan_finish(int* __restrict__ data, const int* __restrict__ bsum,
                            int* __restrict__ cur, int n) {
    __shared__ int offs;
    if (threadIdx.x == 0) {
        int s = 0;
        for (int j = 0; j < blockIdx.x; j++) s += bsum[j];
        offs = s;
    }
    __syncthreads();
    int gid = blockIdx.x * 1024 + threadIdx.x;
    if (gid < n) {
        int v = data[gid] + offs;
        data[gid] = v;
        if (gid < NN) cur[gid] = v;
    }
}

__global__ void fill_csr(const int* __restrict__ src, const int* __restrict__ dst) {
    int e = blockIdx.x * blockDim.x + threadIdx.x;
    if (e >= EE) return;
    int d = dst[e];
    int pos = atomicAdd(&g_cur[d], 1);
    g_csr[pos] = src[e];
}

// ---------------------------------------------------------------------------
// Weight conversion: 7 fp32 [k][n] matrices -> bf16 hi/lo in [n][k] LDSM layout.
// m=0: W1b; m=1..3: convs_Wa[i]; m=4..6: convs_Wb[i]
__global__ void convert_weights(const float* __restrict__ W1b,
                                const float* __restrict__ cWa,
                                const float* __restrict__ cWb) {
    int t = blockIdx.x * blockDim.x + threadIdx.x;
    if (t >= 7 * 16384) return;
    int m = t >> 14, idx = t & 16383;
    int k = idx >> 7, n = idx & 127;
    const float* W = (m == 0) ? W1b : (m <= 3 ? cWa + (m - 1) * 16384 : cWb + (m - 4) * 16384);
    float v = W[idx];
    __nv_bfloat16 hb = __float2bfloat16(v);
    float lo = v - __bfloat162float(hb);
    __nv_bfloat16 lb = __float2bfloat16(lo);
    int off = ls_off(n, k * 2) >> 1;
    g_whi[m * 16384 + off] = hb;
    g_wlo[m * 16384 + off] = lb;
}

// ---------------------------------------------------------------------------
// conv1 aggregation (F_IN=2) via CSR gather: one thread per node
__global__ void aggr2_csr(const float* __restrict__ x, float* __restrict__ out) {
    int n = blockIdx.x * blockDim.x + threadIdx.x;
    if (n >= NN) return;
    float2 acc = *(const float2*)(x + 2 * n);
    int p = g_rowptr[n], e = g_rowptr[n + 1];
    for (; p < e; ++p) {
        int s = g_csr[p];
        float2 v = *(const float2*)(x + 2 * s);
        acc.x += v.x; acc.y += v.y;
    }
    *(float2*)(out + 2 * n) = acc;
}

// H=128 CSR gather, emits bf16 hi/lo tiles in LDSM layout.
__global__ void aggr128_bf16(const float* __restrict__ h) {
    unsigned t = blockIdx.x * blockDim.x + threadIdx.x;
    unsigned n = t >> 5;
    if (n >= NN) return;
    int lane = (int)(t & 31);
    const float* hp = h + lane * 4;
    float4 acc = *(const float4*)(hp + (size_t)n * HH);
    int p = g_rowptr[n], e = g_rowptr[n + 1];
    for (; p + 3 < e; p += 4) {
        int s0 = g_csr[p], s1 = g_csr[p + 1], s2 = g_csr[p + 2], s3 = g_csr[p + 3];
        float4 v0 = *(const float4*)(hp + (size_t)s0 * HH);
        float4 v1 = *(const float4*)(hp + (size_t)s1 * HH);
        float4 v2 = *(const float4*)(hp + (size_t)s2 * HH);
        float4 v3 = *(const float4*)(hp + (size_t)s3 * HH);
        acc.x += (v0.x + v1.x) + (v2.x + v3.x);
        acc.y += (v0.y + v1.y) + (v2.y + v3.y);
        acc.z += (v0.z + v1.z) + (v2.z + v3.z);
        acc.w += (v0.w + v1.w) + (v2.w + v3.w);
    }
    for (; p < e; ++p) {
        int s = g_csr[p];
        float4 v = *(const float4*)(hp + (size_t)s * HH);
        acc.x += v.x; acc.y += v.y; acc.z += v.z; acc.w += v.w;
    }
    int tile = n >> 7, trow = (int)n & 127;
    unsigned h0 = bfpair(acc.x, acc.y), h1 = bfpair(acc.z, acc.w);
    float rx = acc.x - __uint_as_float(h0 << 16);
    float ry = acc.y - __uint_as_float(h0 & 0xFFFF0000u);
    float rz = acc.z - __uint_as_float(h1 << 16);
    float rw = acc.w - __uint_as_float(h1 & 0xFFFF0000u);
    unsigned l0 = bfpair(rx, ry), l1 = bfpair(rz, rw);
    int off = ls_off(trow, lane * 8);   // 8-byte aligned within one 16B chunk
    char* bh = (char*)g_ahi + (size_t)tile * 32768 + off;
    char* bl = (char*)g_alo + (size_t)tile * 32768 + off;
    *(uint2*)bh = make_uint2(h0, h1);
    *(uint2*)bl = make_uint2(l0, l1);
}

// ---------------------------------------------------------------------------
// mma.sync GEMM phase: acc[16][4] += A(128x128) @ W(128x128), bf16x3 split.
// Warp owns rows m0..m0+15. All operands in smem LDSM layout.
__device__ __forceinline__ void mma_phase(unsigned AHI, unsigned ALO,
                                          unsigned WHI, unsigned WLO,
                                          int m0, int lane, float acc[16][4]) {
    const int arow = m0 + (lane & 15);
    const int asel = (lane >> 4) << 4;                 // 0 or 16 bytes
    const int bmi = lane >> 3;
    const int brow_off = ((bmi & 1) << 3) + (lane & 7);
    const int bksel = (bmi >> 1) << 4;
#pragma unroll
    for (int ks = 0; ks < 8; ks++) {
        const int kb = ks * 32;
        unsigned a0, a1, a2, a3, l0, l1, l2, l3;
        ldsm4(a0, a1, a2, a3, AHI + ls_off(arow, kb + asel));
        ldsm4(l0, l1, l2, l3, ALO + ls_off(arow, kb + asel));
#pragma unroll
        for (int nt = 0; nt < 8; nt++) {
            const int brow = nt * 16 + brow_off;
            unsigned bh0, bh1, bh2, bh3, bl0, bl1, bl2, bl3;
            ldsm4(bh0, bh1, bh2, bh3, WHI + ls_off(brow, kb + bksel));
            ldsm4(bl0, bl1, bl2, bl3, WLO + ls_off(brow, kb + bksel));
            const int j = nt * 2;
            mma16816(acc[j],     a0, a1, a2, a3, bh0, bh2);
            mma16816(acc[j],     a0, a1, a2, a3, bl0, bl2);
            mma16816(acc[j],     l0, l1, l2, l3, bh0, bh2);
            mma16816(acc[j + 1], a0, a1, a2, a3, bh1, bh3);
            mma16816(acc[j + 1], a0, a1, a2, a3, bl1, bl3);
            mma16816(acc[j + 1], l0, l1, l2, l3, bh1, bh3);
        }
    }
}

// Fused GIN MLP on tensor cores. CONV1: phase 1 = (N,2)@W1a fp32 direct.
template<bool CONV1>
__global__ void __launch_bounds__(256, 1)
gin_tc(const float* __restrict__ A2, const float* __restrict__ Wa1,
       const __nv_bfloat16* __restrict__ gWahi, const __nv_bfloat16* __restrict__ gWalo,
       const float* __restrict__ ba,
       const __nv_bfloat16* __restrict__ gWbhi, const __nv_bfloat16* __restrict__ gWblo,
       const float* __restrict__ bb, float* __restrict__ C) {
    extern __shared__ char smraw[];
    unsigned sb;
    asm("{ .reg .u64 t; cvta.to.shared.u64 t, %1; cvt.u32.u64 %0, t; }" : "=r"(sb) : "l"(smraw));
    const unsigned base = (sb + 255) & ~255u;
    const unsigned AHI = base, ALO = base + 32768, WHI = base + 65536, WLO = base + 98304;

    const int tid = threadIdx.x, wid = tid >> 5, lane = tid & 31;
    const int m0 = wid * 16;
    const int rowBase = blockIdx.x * 128;

    // ---- stage ----
    if (CONV1) {
        if (tid < 128) {
            int row = tid, grow = rowBase + row;
            float a0 = 0.f, a1 = 0.f;
            if (grow < NN) {
                float2 a = *(const float2*)(A2 + 2 * (size_t)grow);
                a0 = a.x; a1 = a.y;
            }
#pragma unroll 4
            for (int c = 0; c < 128; c += 2) {
                float f0 = fmaxf(fmaf(a0, Wa1[c],     fmaf(a1, Wa1[128 + c],     ba[c])),     0.f);
                float f1 = fmaxf(fmaf(a0, Wa1[c + 1], fmaf(a1, Wa1[128 + c + 1], ba[c + 1])), 0.f);
                split_store(AHI, ALO, row, c, f0, f1);
            }
        } else {
            int i0 = tid - 128;
            const uint4* shi = (const uint4*)gWbhi;
            const uint4* slo = (const uint4*)gWblo;
            for (int i = i0; i < 2048; i += 128) {
                uint4 v = shi[i], u = slo[i];
                asm volatile("st.shared.v4.b32 [%0], {%1,%2,%3,%4};"
                             :: "r"(WHI + i * 16), "r"(v.x), "r"(v.y), "r"(v.z), "r"(v.w) : "memory");
                asm volatile("st.shared.v4.b32 [%0], {%1,%2,%3,%4};"
                             :: "r"(WLO + i * 16), "r"(u.x), "r"(u.y), "r"(u.z), "r"(u.w) : "memory");
            }
        }
    } else {
        const uint4* sA = (const uint4*)(g_ahi + (size_t)blockIdx.x * 16384);
        const uint4* sL = (const uint4*)(g_alo + (size_t)blockIdx.x * 16384);
        const uint4* sW = (const uint4*)gWahi;
        const uint4* sV = (const uint4*)gWalo;
        for (int i = tid; i < 2048; i += 256) {
            uint4 a = sA[i], l = sL[i], w = sW[i], v = sV[i];
            asm volatile("st.shared.v4.b32 [%0], {%1,%2,%3,%4};"
                         :: "r"(AHI + i * 16), "r"(a.x), "r"(a.y), "r"(a.z), "r"(a.w) : "memory");
            asm volatile("st.shared.v4.b32 [%0], {%1,%2,%3,%4};"
                         :: "r"(ALO + i * 16), "r"(l.x), "r"(l.y), "r"(l.z), "r"(l.w) : "memory");
            asm volatile("st.shared.v4.b32 [%0], {%1,%2,%3,%4};"
                         :: "r"(WHI + i * 16), "r"(w.x), "r"(w.y), "r"(w.z), "r"(w.w) : "memory");
            asm volatile("st.shared.v4.b32 [%0], {%1,%2,%3,%4};"
                         :: "r"(WLO + i * 16), "r"(v.x), "r"(v.y), "r"(v.z), "r"(v.w) : "memory");
        }
    }
    __syncthreads();

    float acc[16][4];
#pragma unroll
    for (int j = 0; j < 16; j++)
#pragma unroll
        for (int q = 0; q < 4; q++) acc[j][q] = 0.f;

    if (!CONV1) {
        // ---- phase 1: H1 = relu(A @ Wa + ba) ----
        mma_phase(AHI, ALO, WHI, WLO, m0, lane, acc);
        __syncthreads();  // all warps done reading A before overwrite

        // epilogue: split-convert H1 into AHI/ALO (own rows only)
        {
            const int g = lane >> 2, tt = lane & 3;
#pragma unroll
            for (int j = 0; j < 16; j++) {
                int col = (j >> 1) * 16 + (j & 1) * 8 + 2 * tt;
                float b0 = ba[col], b1 = ba[col + 1];
                split_store(AHI, ALO, m0 + g,     col, fmaxf(acc[j][0] + b0, 0.f),
                                                        fmaxf(acc[j][1] + b1, 0.f));
                split_store(AHI, ALO, m0 + g + 8, col, fmaxf(acc[j][2] + b0, 0.f),
                                                        fmaxf(acc[j][3] + b1, 0.f));
                acc[j][0] = acc[j][1] = acc[j][2] = acc[j][3] = 0.f;
            }
        }
        // reload W buffers with Wb (mma of phase 1 fully done)
        {
            const uint4* shi = (const uint4*)gWbhi;
            const uint4* slo = (const uint4*)gWblo;
            for (int i = tid; i < 2048; i += 256) {
                uint4 v = shi[i], u = slo[i];
                asm volatile("st.shared.v4.b32 [%0], {%1,%2,%3,%4};"
                             :: "r"(WHI + i * 16), "r"(v.x), "r"(v.y), "r"(v.z), "r"(v.w) : "memory");
                asm volatile("st.shared.v4.b32 [%0], {%1,%2,%3,%4};"
                             :: "r"(WLO + i * 16), "r"(u.x), "r"(u.y), "r"(u.z), "r"(u.w) : "memory");
            }
        }
        __syncthreads();
    }

    // ---- phase 2: C = relu(H1 @ Wb + bb) ----
    mma_phase(AHI, ALO, WHI, WLO, m0, lane, acc);

    // final epilogue -> global
    {
        const int g = lane >> 2, tt = lane & 3;
        const int grow0 = rowBase + m0 + g, grow1 = grow0 + 8;
#pragma unroll
        for (int j = 0; j < 16; j++) {
            int col = (j >> 1) * 16 + (j & 1) * 8 + 2 * tt;
            float b0 = bb[col], b1 = bb[col + 1];
            if (grow0 < NN) {
                float2 o = make_float2(fmaxf(acc[j][0] + b0, 0.f), fmaxf(acc[j][1] + b1, 0.f));
                *(float2*)(C + (size_t)grow0 * HH + col) = o;
            }
            if (grow1 < NN) {
                float2 o = make_float2(fmaxf(acc[j][2] + b0, 0.f), fmaxf(acc[j][3] + b1, 0.f));
                *(float2*)(C + (size_t)grow1 * HH + col) = o;
            }
        }
    }
}

// ---------------------------------------------------------------------------
__global__ void pool_scatter(const float* __restrict__ h, const int* __restrict__ seg,
                             float* __restrict__ out, int n) {
    unsigned t = blockIdx.x * blockDim.x + threadIdx.x;
    unsigned i = t >> 5;
    if (i >= (unsigned)n) return;
    int lane = (int)(t & 31);
    int sg = seg[i];
    float4 v = *(const float4*)(h + (size_t)i * HH + lane * 4);
    float* o = out + (size_t)sg * HH + lane * 4;
    atomicAdd(o + 0, v.x);
    atomicAdd(o + 1, v.y);
    atomicAdd(o + 2, v.z);
    atomicAdd(o + 3, v.w);
}

__global__ void head(const float* __restrict__ graph, const float* __restrict__ l1W,
                     const float* __restrict__ l1b, const float* __restrict__ l2W,
                     const float* __restrict__ l2b, float* __restrict__ out) {
    __shared__ float row[HH];
    __shared__ float h1[HH];
    __shared__ float red[HH];
    int g = blockIdx.x;
    int j = threadIdx.x;

    row[j] = graph[g * HH + j];
    __syncthreads();

    float acc = l1b[j];
#pragma unroll 8
    for (int k = 0; k < HH; k++) acc = fmaf(row[k], l1W[k * HH + j], acc);
    h1[j] = fmaxf(acc, 0.f);
    __syncthreads();

    float acc2 = l2b[j];
#pragma unroll 8
    for (int k = 0; k < HH; k++) acc2 = fmaf(h1[k], l2W[k * HH + j], acc2);

    red[j] = acc2;
    __syncthreads();
    for (int s = 64; s > 0; s >>= 1) {
        if (j < s) red[j] = fmaxf(red[j], red[j + s]);
        __syncthreads();
    }
    float m = red[0];
    __syncthreads();
    red[j] = expf(acc2 - m);
    __syncthreads();
    for (int s = 64; s > 0; s >>= 1) {
        if (j < s) red[j] += red[j + s];
        __syncthreads();
    }
    float lse = m + logf(red[0]);
    out[g * HH + j] = acc2 - lse;
}

// ---------------------------------------------------------------------------
extern "C" void kernel_launch(void* const* d_in, const int* in_sizes, int n_in,
                              void* d_out, int out_size) {
    const float* x   = (const float*)d_in[0];
    const int*   ei  = (const int*)  d_in[1];
    const int*   n2s = (const int*)  d_in[2];
    const int*   s2g = (const int*)  d_in[3];
    const float* W1a = (const float*)d_in[4];
    const float* b1a = (const float*)d_in[5];
    const float* W1b = (const float*)d_in[6];
    const float* b1b = (const float*)d_in[7];
    const float* cWa = (const float*)d_in[8];
    const float* cba = (const float*)d_in[9];
    const float* cWb = (const float*)d_in[10];
    const float* cbb = (const float*)d_in[11];
    const float* l1W = (const float*)d_in[12];
    const float* l1b = (const float*)d_in[13];
    const float* l2W = (const float*)d_in[14];
    const float* l2b = (const float*)d_in[15];
    float* out = (float*)d_out;

    const int* src = ei;
    const int* dst = ei + EE;

    float *ph, *pag2, *ppool;
    __nv_bfloat16 *pwhi, *pwlo;
    int *prp, *pbs, *pcur;
    cudaGetSymbolAddress((void**)&ph,    g_h);
    cudaGetSymbolAddress((void**)&pag2,  g_aggr2);
    cudaGetSymbolAddress((void**)&ppool, g_pool);
    cudaGetSymbolAddress((void**)&pwhi,  g_whi);
    cudaGetSymbolAddress((void**)&pwlo,  g_wlo);
    cudaGetSymbolAddress((void**)&prp,   g_rowptr);
    cudaGetSymbolAddress((void**)&pbs,   g_bsum);
    cudaGetSymbolAddress((void**)&pcur,  g_cur);

    float* psub = ppool;
    float* pgr  = ppool + SS * HH;

    const int TB = 256;
    const int nScan = NN + 1;
    const int scanBlocks = (nScan + 1023) / 1024;
    const int initN = (SS + GG) * HH / 4;
    const int SMEM = 4 * 32768 + 256;  // 131328

    cudaFuncSetAttribute(gin_tc<true>,  cudaFuncAttributeMaxDynamicSharedMemorySize, SMEM);
    cudaFuncSetAttribute(gin_tc<false>, cudaFuncAttributeMaxDynamicSharedMemorySize, SMEM);

    // ---- init + weight convert + CSR build ----
    init_zero<<<(initN + TB - 1) / TB, TB>>>(prp, (float4*)ppool);
    convert_weights<<<(7 * 16384 + TB - 1) / TB, TB>>>(W1b, cWa, cWb);
    hist_dst<<<(EE + TB - 1) / TB, TB>>>(dst);
    scan1<<<scanBlocks, 1024>>>(prp, pbs, nScan);
    scan_finish<<<scanBlocks, 1024>>>(prp, pbs, pcur, nScan);
    fill_csr<<<(EE + TB - 1) / TB, TB>>>(src, dst);

    // ---- conv1 ----
    aggr2_csr<<<(NN + TB - 1) / TB, TB>>>(x, pag2);
    gin_tc<true><<<NTILES, TB, SMEM>>>(pag2, W1a, nullptr, nullptr, b1a,
                                       pwhi, pwlo, b1b, ph);

    // ---- convs 2..4 ----
    for (int i = 0; i < 3; i++) {
        aggr128_bf16<<<(NN * 32 + TB - 1) / TB, TB>>>(ph);
        gin_tc<false><<<NTILES, TB, SMEM>>>(nullptr, nullptr,
                                            pwhi + (1 + i) * 16384, pwlo + (1 + i) * 16384,
                                            cba + i * HH,
                                            pwhi + (4 + i) * 16384, pwlo + (4 + i) * 16384,
                                            cbb + i * HH, ph);
    }

    // ---- nested pooling ----
    pool_scatter<<<(NN * 32 + TB - 1) / TB, TB>>>(ph, n2s, psub, NN);
    pool_scatter<<<(SS * 32 + TB - 1) / TB, TB>>>(psub, s2g, pgr, SS);

    // ---- head ----
    head<<<GG, HH>>>(pgr, l1W, l1b, l2W, l2b, out);
}

// round 9
// speedup vs baseline: 1.6791x; 1.0756x over previous
#include <cuda_runtime.h>
#include <cuda_bf16.h>
#include <math.h>

#define NN 50000
#define EE 800000
#define HH 128
#define SS 5000
#define GG 64
#define NTILES 391   // ceil(NN/128)

// Scratch (device globals: no allocation allowed)
__device__ float g_h    [NN*HH];
__device__ float g_aggr2[NN*2];
__device__ float g_pool [(SS+GG)*HH];
__device__ __nv_bfloat16 g_ahi[NTILES*16384];  // per-tile LDSM-layout A hi
__device__ __nv_bfloat16 g_alo[NTILES*16384];
__device__ __nv_bfloat16 g_whi[7*16384];       // weights, [n][k] LDSM layout
__device__ __nv_bfloat16 g_wlo[7*16384];
__device__ int   g_rowptr[NN+1];
__device__ int   g_cur[NN];
__device__ int   g_csr[EE];
__device__ int   g_bsum[64];

// ---------------------------------------------------------------------------
// LDSM-friendly swizzled layout: 128 rows x 256 bytes (128 bf16). 16B chunks
// XOR-swizzled by row&7 -> ldmatrix reads of 8 rows are bank-conflict-free.
__device__ __host__ __forceinline__ int ls_off(int row, int kbyte) {
    return row * 256 + ((((kbyte >> 4) ^ row) & 7) << 4) + (kbyte & 15) + (kbyte & ~127);
}

__device__ __forceinline__ unsigned bfpair(float f0, float f1) {  // {lo:f0, hi:f1}
    unsigned r;
    asm("cvt.rn.bf16x2.f32 %0, %1, %2;" : "=r"(r) : "f"(f1), "f"(f0));
    return r;
}

__device__ __forceinline__ void ldsm4(unsigned& r0, unsigned& r1, unsigned& r2,
                                      unsigned& r3, unsigned addr) {
    asm volatile("ldmatrix.sync.aligned.m8n8.x4.shared.b16 {%0,%1,%2,%3}, [%4];"
                 : "=r"(r0), "=r"(r1), "=r"(r2), "=r"(r3) : "r"(addr));
}

__device__ __forceinline__ void mma16816(float* c, unsigned a0, unsigned a1,
                                         unsigned a2, unsigned a3,
                                         unsigned b0, unsigned b1) {
    asm volatile("mma.sync.aligned.m16n8k16.row.col.f32.bf16.bf16.f32 "
                 "{%0,%1,%2,%3}, {%4,%5,%6,%7}, {%8,%9}, {%0,%1,%2,%3};"
                 : "+f"(c[0]), "+f"(c[1]), "+f"(c[2]), "+f"(c[3])
                 : "r"(a0), "r"(a1), "r"(a2), "r"(a3), "r"(b0), "r"(b1));
}

__device__ __forceinline__ void split_store(unsigned AHI, unsigned ALO,
                                            int row, int col, float f0, float f1) {
    unsigned hp = bfpair(f0, f1);
    float r0 = f0 - __uint_as_float(hp << 16);
    float r1 = f1 - __uint_as_float(hp & 0xFFFF0000u);
    unsigned lp = bfpair(r0, r1);
    int off = ls_off(row, col * 2);
    asm volatile("st.shared.b32 [%0], %1;" :: "r"(AHI + off), "r"(hp) : "memory");
    asm volatile("st.shared.b32 [%0], %1;" :: "r"(ALO + off), "r"(lp) : "memory");
}

// ---------------------------------------------------------------------------
__global__ void init_zero(int* __restrict__ rowptr, float4* __restrict__ pool) {
    int i = blockIdx.x * blockDim.x + threadIdx.x;
    if (i < NN + 1) rowptr[i] = 0;
    if (i < (SS + GG) * HH / 4) pool[i] = make_float4(0.f, 0.f, 0.f, 0.f);
}

__global__ void hist_dst(const int* __restrict__ dst) {
    int e = blockIdx.x * blockDim.x + threadIdx.x;
    if (e < EE) atomicAdd(&g_rowptr[dst[e] + 1], 1);
}

__global__ void scan1(int* __restrict__ data, int* __restrict__ bsum, int n) {
    __shared__ int sh[1024];
    int gid = blockIdx.x * 1024 + threadIdx.x;
    int v = (gid < n) ? data[gid] : 0;
    sh[threadIdx.x] = v;
    __syncthreads();
    for (int off = 1; off < 1024; off <<= 1) {
        int t = (threadIdx.x >= off) ? sh[threadIdx.x - off] : 0;
        __syncthreads();
        sh[threadIdx.x] += t;
        __syncthreads();
    }
    if (gid < n) data[gid] = sh[threadIdx.x];
    if (threadIdx.x == 1023) bsum[blockIdx.x] = sh[1023];
}

__global__ void scan_finish(int* __restrict__ data, const int* __restrict__ bsum,
                            int* __restrict__ cur, int n) {
    __shared__ int offs;
    if (threadIdx.x == 0) {
        int s = 0;
        for (int j = 0; j < blockIdx.x; j++) s += bsum[j];
        offs = s;
    }
    __syncthreads();
    int gid = blockIdx.x * 1024 + threadIdx.x;
    if (gid < n) {
        int v = data[gid] + offs;
        data[gid] = v;
        if (gid < NN) cur[gid] = v;
    }
}

__global__ void fill_csr(const int* __restrict__ src, const int* __restrict__ dst) {
    int e = blockIdx.x * blockDim.x + threadIdx.x;
    if (e >= EE) return;
    int d = dst[e];
    int pos = atomicAdd(&g_cur[d], 1);
    g_csr[pos] = src[e];
}

// ---------------------------------------------------------------------------
// Weight conversion: 7 fp32 [k][n] matrices -> bf16 hi/lo in [n][k] LDSM layout.
__global__ void convert_weights(const float* __restrict__ W1b,
                                const float* __restrict__ cWa,
                                const float* __restrict__ cWb) {
    int t = blockIdx.x * blockDim.x + threadIdx.x;
    if (t >= 7 * 16384) return;
    int m = t >> 14, idx = t & 16383;
    int k = idx >> 7, n = idx & 127;
    const float* W = (m == 0) ? W1b : (m <= 3 ? cWa + (m - 1) * 16384 : cWb + (m - 4) * 16384);
    float v = W[idx];
    __nv_bfloat16 hb = __float2bfloat16(v);
    float lo = v - __bfloat162float(hb);
    __nv_bfloat16 lb = __float2bfloat16(lo);
    int off = ls_off(n, k * 2) >> 1;
    g_whi[m * 16384 + off] = hb;
    g_wlo[m * 16384 + off] = lb;
}

// ---------------------------------------------------------------------------
__global__ void aggr2_csr(const float* __restrict__ x, float* __restrict__ out) {
    int n = blockIdx.x * blockDim.x + threadIdx.x;
    if (n >= NN) return;
    float2 acc = *(const float2*)(x + 2 * n);
    int p = g_rowptr[n], e = g_rowptr[n + 1];
    for (; p < e; ++p) {
        int s = g_csr[p];
        float2 v = *(const float2*)(x + 2 * s);
        acc.x += v.x; acc.y += v.y;
    }
    *(float2*)(out + 2 * n) = acc;
}

// H=128 CSR gather, emits bf16 hi/lo tiles in LDSM layout.
__global__ void aggr128_bf16(const float* __restrict__ h) {
    unsigned t = blockIdx.x * blockDim.x + threadIdx.x;
    unsigned n = t >> 5;
    if (n >= NN) return;
    int lane = (int)(t & 31);
    const float* hp = h + lane * 4;
    float4 acc = *(const float4*)(hp + (size_t)n * HH);
    int p = g_rowptr[n], e = g_rowptr[n + 1];
    for (; p + 3 < e; p += 4) {
        int s0 = g_csr[p], s1 = g_csr[p + 1], s2 = g_csr[p + 2], s3 = g_csr[p + 3];
        float4 v0 = *(const float4*)(hp + (size_t)s0 * HH);
        float4 v1 = *(const float4*)(hp + (size_t)s1 * HH);
        float4 v2 = *(const float4*)(hp + (size_t)s2 * HH);
        float4 v3 = *(const float4*)(hp + (size_t)s3 * HH);
        acc.x += (v0.x + v1.x) + (v2.x + v3.x);
        acc.y += (v0.y + v1.y) + (v2.y + v3.y);
        acc.z += (v0.z + v1.z) + (v2.z + v3.z);
        acc.w += (v0.w + v1.w) + (v2.w + v3.w);
    }
    for (; p < e; ++p) {
        int s = g_csr[p];
        float4 v = *(const float4*)(hp + (size_t)s * HH);
        acc.x += v.x; acc.y += v.y; acc.z += v.z; acc.w += v.w;
    }
    int tile = n >> 7, trow = (int)n & 127;
    unsigned h0 = bfpair(acc.x, acc.y), h1 = bfpair(acc.z, acc.w);
    float rx = acc.x - __uint_as_float(h0 << 16);
    float ry = acc.y - __uint_as_float(h0 & 0xFFFF0000u);
    float rz = acc.z - __uint_as_float(h1 << 16);
    float rw = acc.w - __uint_as_float(h1 & 0xFFFF0000u);
    unsigned l0 = bfpair(rx, ry), l1 = bfpair(rz, rw);
    int off = ls_off(trow, lane * 8);
    char* bh = (char*)g_ahi + (size_t)tile * 32768 + off;
    char* bl = (char*)g_alo + (size_t)tile * 32768 + off;
    *(uint2*)bh = make_uint2(h0, h1);
    *(uint2*)bl = make_uint2(l0, l1);
}

// ---------------------------------------------------------------------------
// mma.sync GEMM phase, warp tile 32x64: acc[(mi*4+nt)*2+h][4].
// 4 m-groups x 2 n-groups; per k-slice: 4 A-LDSM + 8 B-LDSM (was 2+16).
__device__ __forceinline__ void mma_phase(unsigned AHI, unsigned ALO,
                                          unsigned WHI, unsigned WLO,
                                          int m0, int n0, int lane, float acc[16][4]) {
    const int arow = (lane & 15);
    const int asel = (lane >> 4) << 4;                 // 0 or 16 bytes
    const int bmi = lane >> 3;
    const int brow_off = ((bmi & 1) << 3) + (lane & 7);
    const int bksel = (bmi >> 1) << 4;
#pragma unroll
    for (int ks = 0; ks < 8; ks++) {
        const int kb = ks * 32;
        unsigned a[2][4], l[2][4];
#pragma unroll
        for (int mi = 0; mi < 2; mi++) {
            int r = m0 + mi * 16 + arow;
            ldsm4(a[mi][0], a[mi][1], a[mi][2], a[mi][3], AHI + ls_off(r, kb + asel));
            ldsm4(l[mi][0], l[mi][1], l[mi][2], l[mi][3], ALO + ls_off(r, kb + asel));
        }
#pragma unroll
        for (int nt = 0; nt < 4; nt++) {
            const int brow = n0 + nt * 16 + brow_off;
            unsigned bh0, bh1, bh2, bh3, bl0, bl1, bl2, bl3;
            ldsm4(bh0, bh1, bh2, bh3, WHI + ls_off(brow, kb + bksel));
            ldsm4(bl0, bl1, bl2, bl3, WLO + ls_off(brow, kb + bksel));
#pragma unroll
            for (int mi = 0; mi < 2; mi++) {
                const int j = (mi * 4 + nt) * 2;
                mma16816(acc[j],     a[mi][0], a[mi][1], a[mi][2], a[mi][3], bh0, bh2);
                mma16816(acc[j],     a[mi][0], a[mi][1], a[mi][2], a[mi][3], bl0, bl2);
                mma16816(acc[j],     l[mi][0], l[mi][1], l[mi][2], l[mi][3], bh0, bh2);
                mma16816(acc[j + 1], a[mi][0], a[mi][1], a[mi][2], a[mi][3], bh1, bh3);
                mma16816(acc[j + 1], a[mi][0], a[mi][1], a[mi][2], a[mi][3], bl1, bl3);
                mma16816(acc[j + 1], l[mi][0], l[mi][1], l[mi][2], l[mi][3], bh1, bh3);
            }
        }
    }
}

// Fused GIN MLP on tensor cores. CONV1: phase 1 = (N,2)@W1a fp32 direct.
template<bool CONV1>
__global__ void __launch_bounds__(256, 1)
gin_tc(const float* __restrict__ A2, const float* __restrict__ Wa1,
       const __nv_bfloat16* __restrict__ gWahi, const __nv_bfloat16* __restrict__ gWalo,
       const float* __restrict__ ba,
       const __nv_bfloat16* __restrict__ gWbhi, const __nv_bfloat16* __restrict__ gWblo,
       const float* __restrict__ bb, float* __restrict__ C) {
    extern __shared__ char smraw[];
    unsigned sb;
    asm("{ .reg .u64 t; cvta.to.shared.u64 t, %1; cvt.u32.u64 %0, t; }" : "=r"(sb) : "l"(smraw));
    const unsigned base = (sb + 255) & ~255u;
    const unsigned AHI = base, ALO = base + 32768, WHI = base + 65536, WLO = base + 98304;

    const int tid = threadIdx.x, wid = tid >> 5, lane = tid & 31;
    const int m0 = (wid & 3) * 32, n0 = (wid >> 2) * 64;
    const int rowBase = blockIdx.x * 128;

    // ---- stage ----
    if (CONV1) {
        if (tid < 128) {
            int row = tid, grow = rowBase + row;
            float a0 = 0.f, a1 = 0.f;
            if (grow < NN) {
                float2 a = *(const float2*)(A2 + 2 * (size_t)grow);
                a0 = a.x; a1 = a.y;
            }
#pragma unroll 4
            for (int c = 0; c < 128; c += 2) {
                float f0 = fmaxf(fmaf(a0, Wa1[c],     fmaf(a1, Wa1[128 + c],     ba[c])),     0.f);
                float f1 = fmaxf(fmaf(a0, Wa1[c + 1], fmaf(a1, Wa1[128 + c + 1], ba[c + 1])), 0.f);
                split_store(AHI, ALO, row, c, f0, f1);
            }
        } else {
            int i0 = tid - 128;
            const uint4* shi = (const uint4*)gWbhi;
            const uint4* slo = (const uint4*)gWblo;
            for (int i = i0; i < 2048; i += 128) {
                uint4 v = shi[i], u = slo[i];
                asm volatile("st.shared.v4.b32 [%0], {%1,%2,%3,%4};"
                             :: "r"(WHI + i * 16), "r"(v.x), "r"(v.y), "r"(v.z), "r"(v.w) : "memory");
                asm volatile("st.shared.v4.b32 [%0], {%1,%2,%3,%4};"
                             :: "r"(WLO + i * 16), "r"(u.x), "r"(u.y), "r"(u.z), "r"(u.w) : "memory");
            }
        }
    } else {
        const uint4* sA = (const uint4*)(g_ahi + (size_t)blockIdx.x * 16384);
        const uint4* sL = (const uint4*)(g_alo + (size_t)blockIdx.x * 16384);
        const uint4* sW = (const uint4*)gWahi;
        const uint4* sV = (const uint4*)gWalo;
        for (int i = tid; i < 2048; i += 256) {
            uint4 a = sA[i], l = sL[i], w = sW[i], v = sV[i];
            asm volatile("st.shared.v4.b32 [%0], {%1,%2,%3,%4};"
                         :: "r"(AHI + i * 16), "r"(a.x), "r"(a.y), "r"(a.z), "r"(a.w) : "memory");
            asm volatile("st.shared.v4.b32 [%0], {%1,%2,%3,%4};"
                         :: "r"(ALO + i * 16), "r"(l.x), "r"(l.y), "r"(l.z), "r"(l.w) : "memory");
            asm volatile("st.shared.v4.b32 [%0], {%1,%2,%3,%4};"
                         :: "r"(WHI + i * 16), "r"(w.x), "r"(w.y), "r"(w.z), "r"(w.w) : "memory");
            asm volatile("st.shared.v4.b32 [%0], {%1,%2,%3,%4};"
                         :: "r"(WLO + i * 16), "r"(v.x), "r"(v.y), "r"(v.z), "r"(v.w) : "memory");
        }
    }
    __syncthreads();

    float acc[16][4];
#pragma unroll
    for (int j = 0; j < 16; j++)
#pragma unroll
        for (int q = 0; q < 4; q++) acc[j][q] = 0.f;

    if (!CONV1) {
        // ---- phase 1: H1 = relu(A @ Wa + ba) ----
        mma_phase(AHI, ALO, WHI, WLO, m0, n0, lane, acc);
        __syncthreads();  // all warps done reading A/W before overwrite

        // epilogue: split-convert H1 into AHI/ALO (own 32x64 block)
        {
            const int g = lane >> 2, tt = lane & 3;
#pragma unroll
            for (int j = 0; j < 16; j++) {
                int mi = j >> 3, nt = (j >> 1) & 3, hf = j & 1;
                int col = n0 + nt * 16 + hf * 8 + 2 * tt;
                int r0 = m0 + mi * 16 + g;
                float b0 = ba[col], b1 = ba[col + 1];
                split_store(AHI, ALO, r0,     col, fmaxf(acc[j][0] + b0, 0.f),
                                                    fmaxf(acc[j][1] + b1, 0.f));
                split_store(AHI, ALO, r0 + 8, col, fmaxf(acc[j][2] + b0, 0.f),
                                                    fmaxf(acc[j][3] + b1, 0.f));
                acc[j][0] = acc[j][1] = acc[j][2] = acc[j][3] = 0.f;
            }
        }
        // reload W buffers with Wb
        {
            const uint4* shi = (const uint4*)gWbhi;
            const uint4* slo = (const uint4*)gWblo;
            for (int i = tid; i < 2048; i += 256) {
                uint4 v = shi[i], u = slo[i];
                asm volatile("st.shared.v4.b32 [%0], {%1,%2,%3,%4};"
                             :: "r"(WHI + i * 16), "r"(v.x), "r"(v.y), "r"(v.z), "r"(v.w) : "memory");
                asm volatile("st.shared.v4.b32 [%0], {%1,%2,%3,%4};"
                             :: "r"(WLO + i * 16), "r"(u.x), "r"(u.y), "r"(u.z), "r"(u.w) : "memory");
            }
        }
        __syncthreads();
    }

    // ---- phase 2: C = relu(H1 @ Wb + bb) ----
    mma_phase(AHI, ALO, WHI, WLO, m0, n0, lane, acc);

    // final epilogue -> global
    {
        const int g = lane >> 2, tt = lane & 3;
#pragma unroll
        for (int j = 0; j < 16; j++) {
            int mi = j >> 3, nt = (j >> 1) & 3, hf = j & 1;
            int col = n0 + nt * 16 + hf * 8 + 2 * tt;
            int grow0 = rowBase + m0 + mi * 16 + g, grow1 = grow0 + 8;
            float b0 = bb[col], b1 = bb[col + 1];
            if (grow0 < NN) {
                float2 o = make_float2(fmaxf(acc[j][0] + b0, 0.f), fmaxf(acc[j][1] + b1, 0.f));
                *(float2*)(C + (size_t)grow0 * HH + col) = o;
            }
            if (grow1 < NN) {
                float2 o = make_float2(fmaxf(acc[j][2] + b0, 0.f), fmaxf(acc[j][3] + b1, 0.f));
                *(float2*)(C + (size_t)grow1 * HH + col) = o;
            }
        }
    }
}

// ---------------------------------------------------------------------------
__global__ void pool_scatter(const float* __restrict__ h, const int* __restrict__ seg,
                             float* __restrict__ out, int n) {
    unsigned t = blockIdx.x * blockDim.x + threadIdx.x;
    unsigned i = t >> 5;
    if (i >= (unsigned)n) return;
    int lane = (int)(t & 31);
    int sg = seg[i];
    float4 v = *(const float4*)(h + (size_t)i * HH + lane * 4);
    float* o = out + (size_t)sg * HH + lane * 4;
    atomicAdd(o + 0, v.x);
    atomicAdd(o + 1, v.y);
    atomicAdd(o + 2, v.z);
    atomicAdd(o + 3, v.w);
}

__global__ void head(const float* __restrict__ graph, const float* __restrict__ l1W,
                     const float* __restrict__ l1b, const float* __restrict__ l2W,
                     const float* __restrict__ l2b, float* __restrict__ out) {
    __shared__ float row[HH];
    __shared__ float h1[HH];
    __shared__ float red[HH];
    int g = blockIdx.x;
    int j = threadIdx.x;

    row[j] = graph[g * HH + j];
    __syncthreads();

    float acc = l1b[j];
#pragma unroll 8
    for (int k = 0; k < HH; k++) acc = fmaf(row[k], l1W[k * HH + j], acc);
    h1[j] = fmaxf(acc, 0.f);
    __syncthreads();

    float acc2 = l2b[j];
#pragma unroll 8
    for (int k = 0; k < HH; k++) acc2 = fmaf(h1[k], l2W[k * HH + j], acc2);

    red[j] = acc2;
    __syncthreads();
    for (int s = 64; s > 0; s >>= 1) {
        if (j < s) red[j] = fmaxf(red[j], red[j + s]);
        __syncthreads();
    }
    float m = red[0];
    __syncthreads();
    red[j] = expf(acc2 - m);
    __syncthreads();
    for (int s = 64; s > 0; s >>= 1) {
        if (j < s) red[j] += red[j + s];
        __syncthreads();
    }
    float lse = m + logf(red[0]);
    out[g * HH + j] = acc2 - lse;
}

// ---------------------------------------------------------------------------
extern "C" void kernel_launch(void* const* d_in, const int* in_sizes, int n_in,
                              void* d_out, int out_size) {
    const float* x   = (const float*)d_in[0];
    const int*   ei  = (const int*)  d_in[1];
    const int*   n2s = (const int*)  d_in[2];
    const int*   s2g = (const int*)  d_in[3];
    const float* W1a = (const float*)d_in[4];
    const float* b1a = (const float*)d_in[5];
    const float* W1b = (const float*)d_in[6];
    const float* b1b = (const float*)d_in[7];
    const float* cWa = (const float*)d_in[8];
    const float* cba = (const float*)d_in[9];
    const float* cWb = (const float*)d_in[10];
    const float* cbb = (const float*)d_in[11];
    const float* l1W = (const float*)d_in[12];
    const float* l1b = (const float*)d_in[13];
    const float* l2W = (const float*)d_in[14];
    const float* l2b = (const float*)d_in[15];
    float* out = (float*)d_out;

    const int* src = ei;
    const int* dst = ei + EE;

    float *ph, *pag2, *ppool;
    __nv_bfloat16 *pwhi, *pwlo;
    int *prp, *pbs, *pcur;
    cudaGetSymbolAddress((void**)&ph,    g_h);
    cudaGetSymbolAddress((void**)&pag2,  g_aggr2);
    cudaGetSymbolAddress((void**)&ppool, g_pool);
    cudaGetSymbolAddress((void**)&pwhi,  g_whi);
    cudaGetSymbolAddress((void**)&pwlo,  g_wlo);
    cudaGetSymbolAddress((void**)&prp,   g_rowptr);
    cudaGetSymbolAddress((void**)&pbs,   g_bsum);
    cudaGetSymbolAddress((void**)&pcur,  g_cur);

    float* psub = ppool;
    float* pgr  = ppool + SS * HH;

    const int TB = 256;
    const int nScan = NN + 1;
    const int scanBlocks = (nScan + 1023) / 1024;
    const int initN = (SS + GG) * HH / 4;
    const int SMEM = 4 * 32768 + 256;  // 131328

    cudaFuncSetAttribute(gin_tc<true>,  cudaFuncAttributeMaxDynamicSharedMemorySize, SMEM);
    cudaFuncSetAttribute(gin_tc<false>, cudaFuncAttributeMaxDynamicSharedMemorySize, SMEM);

    // ---- init + weight convert + CSR build ----
    init_zero<<<(initN + TB - 1) / TB, TB>>>(prp, (float4*)ppool);
    convert_weights<<<(7 * 16384 + TB - 1) / TB, TB>>>(W1b, cWa, cWb);
    hist_dst<<<(EE + TB - 1) / TB, TB>>>(dst);
    scan1<<<scanBlocks, 1024>>>(prp, pbs, nScan);
    scan_finish<<<scanBlocks, 1024>>>(prp, pbs, pcur, nScan);
    fill_csr<<<(EE + TB - 1) / TB, TB>>>(src, dst);

    // ---- conv1 ----
    aggr2_csr<<<(NN + TB - 1) / TB, TB>>>(x, pag2);
    gin_tc<true><<<NTILES, TB, SMEM>>>(pag2, W1a, nullptr, nullptr, b1a,
                                       pwhi, pwlo, b1b, ph);

    // ---- convs 2..4 ----
    for (int i = 0; i < 3; i++) {
        aggr128_bf16<<<(NN * 32 + TB - 1) / TB, TB>>>(ph);
        gin_tc<false><<<NTILES, TB, SMEM>>>(nullptr, nullptr,
                                            pwhi + (1 + i) * 16384, pwlo + (1 + i) * 16384,
                                            cba + i * HH,
                                            pwhi + (4 + i) * 16384, pwlo + (4 + i) * 16384,
                                            cbb + i * HH, ph);
    }

    // ---- nested pooling ----
    pool_scatter<<<(NN * 32 + TB - 1) / TB, TB>>>(ph, n2s, psub, NN);
    pool_scatter<<<(SS * 32 + TB - 1) / TB, TB>>>(psub, s2g, pgr, SS);

    // ---- head ----
    head<<<GG, HH>>>(pgr, l1W, l1b, l2W, l2b, out);
}